// round 14
// baseline (speedup 1.0000x reference)
#include <cuda_runtime.h>
#include <cuda_bf16.h>
#include <cuda_pipeline.h>

// MultiBoxLoss (SSD), fully fused: one CTA per batch row.
// Row streamed through a per-warp 2-stage cp.async smem pipeline (deep MLP),
// per-anchor CE kept in registers, block-parallel 3-level radix select of the
// k-th largest negative CE (validated; bisection fallback), per-row sum, last
// CTA reduces the 128 rows and writes the scalar (resets done counter).

#define ROWS 128
#define AA   8732
#define CC   21
#define CPR  273            // chunks of 32 anchors: 272 full + 1 of 28
#define NT   1024
#define PER  9              // chunks per warp (warps 0..16: 9, 17..31: 8)

__device__ double   g_rowsum[ROWS];
__device__ int      g_rowpos[ROWS];
__device__ unsigned g_done = 0u;   // reset by the finalizing block each run

// Warp-aggregated smem histogram add.
__device__ __forceinline__ void hist_add(unsigned* h, unsigned bin, unsigned mask)
{
    const unsigned peers  = __match_any_sync(mask, bin);
    const unsigned leader = __ffs(peers) - 1u;
    if ((threadIdx.x & 31u) == leader)
        atomicAdd(&h[bin], __popc(peers));
}

// Block-wide inclusive prefix sum over 1024 values (one per thread).
// Contains 2 __syncthreads. s_w must hold 32 unsigneds.
__device__ __forceinline__ unsigned block_scan_incl(
    unsigned v, unsigned* s_w, int wid, unsigned lane)
{
    #pragma unroll
    for (int off = 1; off < 32; off <<= 1) {
        const unsigned x = __shfl_up_sync(0xFFFFFFFFu, v, off);
        if (lane >= off) v += x;
    }
    if (lane == 31) s_w[wid] = v;
    __syncthreads();
    if (wid == 0) {
        unsigned t = s_w[lane];
        #pragma unroll
        for (int off = 1; off < 32; off <<= 1) {
            const unsigned x = __shfl_up_sync(0xFFFFFFFFu, t, off);
            if (lane >= off) t += x;
        }
        s_w[lane] = t;  // inclusive warp totals
    }
    __syncthreads();
    if (wid > 0) v += s_w[wid - 1];
    return v;
}

extern __shared__ float dynbuf[];   // 32 warps * 2 stages * 672 floats = 172032 B

__global__ __launch_bounds__(NT, 1) void mbl_fused(
    const float* __restrict__ conf,
    const float* __restrict__ loc,
    const int*   __restrict__ lab,
    const float* __restrict__ gloc,
    float* __restrict__ out)
{
    const int b    = blockIdx.x;
    const int tid  = threadIdx.x;
    const int wid  = tid >> 5;
    const unsigned lane = tid & 31u;

    __shared__ unsigned s_hist[2048];
    __shared__ unsigned s_w[32];
    __shared__ int      s_selbin;
    __shared__ unsigned s_selrank;
    __shared__ int      s_pos;
    __shared__ double   s_psum;
    __shared__ float    s_fsum;
    __shared__ unsigned s_cgt;
    __shared__ unsigned s_vgt, s_vge;
    __shared__ int      s_last;
    __shared__ double   s_d[4];
    __shared__ int      s_i[4];

    if (tid == 0) {
        s_pos = 0; s_psum = 0.0; s_fsum = 0.f; s_cgt = 0u;
        s_vgt = 0u; s_vge = 0u; s_last = 0;
    }

    const size_t rowbase = (size_t)b * AA;

    float ce_reg[PER];
    float psum   = 0.f;
    int   poscnt = 0;

    // Prologue: stage 0 <- chunk (wid). wid<=31 < 272, so always full (168 q4).
    {
        float4* st = (float4*)(dynbuf + (wid * 2 + 0) * 672);
        const float4* src = (const float4*)(conf + (rowbase + (size_t)wid * 32) * CC);
        #pragma unroll
        for (int t = 0; t < 6; t++) {
            const int e = (int)lane + 32 * t;
            if (e < 168) __pipeline_memcpy_async(st + e, src + e, 16);
        }
        __pipeline_commit();
    }

    #pragma unroll
    for (int i = 0; i < PER; i++) {
        ce_reg[i] = 0.f;
        const int ch = wid + 32 * i;          // uniform per warp
        if (ch < CPR) {
            const int na = (ch == CPR - 1) ? (AA - (CPR - 1) * 32) : 32;  // 28 or 32
            const size_t abase = rowbase + (size_t)ch * 32;

            // Issue next chunk into the other stage.
            const int chn = ch + 32;
            const bool hasnext = (i + 1 < PER) && (chn < CPR);
            if (hasnext) {
                const int n4n = (((chn == CPR - 1) ? (AA - (CPR - 1) * 32) : 32) * CC) >> 2;
                float4* stn = (float4*)(dynbuf + (wid * 2 + ((i + 1) & 1)) * 672);
                const float4* srcn = (const float4*)(conf + (rowbase + (size_t)chn * 32) * CC);
                #pragma unroll
                for (int t = 0; t < 6; t++) {
                    const int e = (int)lane + 32 * t;
                    if (e < n4n) __pipeline_memcpy_async(stn + e, srcn + e, 16);
                }
            }
            __pipeline_commit();
            if (hasnext) __pipeline_wait_prior(1);
            else         __pipeline_wait_prior(0);
            __syncwarp();

            const float* sw = dynbuf + (wid * 2 + (i & 1)) * 672;

            if ((int)lane < na) {
                const size_t idx = abase + (size_t)lane;
                const int lb = __ldg(lab + idx);
                const float* vp = sw + lane * CC;
                float m = vp[0];
                #pragma unroll
                for (int t2 = 1; t2 < CC; t2++) m = fmaxf(m, vp[t2]);
                float s = 0.f;
                #pragma unroll
                for (int t2 = 0; t2 < CC; t2++) s += __expf(vp[t2] - m);
                const float ce = m + __logf(s) - vp[lb];

                if (lb > 0) {
                    poscnt++;
                    float p = ce;
                    const float4 l4 = __ldg((const float4*)loc  + idx);
                    const float4 g4 = __ldg((const float4*)gloc + idx);
                    float d, ad;
                    d = l4.x - g4.x; ad = fabsf(d); p += (ad < 1.f) ? 0.5f * d * d : ad - 0.5f;
                    d = l4.y - g4.y; ad = fabsf(d); p += (ad < 1.f) ? 0.5f * d * d : ad - 0.5f;
                    d = l4.z - g4.z; ad = fabsf(d); p += (ad < 1.f) ? 0.5f * d * d : ad - 0.5f;
                    d = l4.w - g4.w; ad = fabsf(d); p += (ad < 1.f) ? 0.5f * d * d : ad - 0.5f;
                    psum += p;
                } else {
                    ce_reg[i] = ce;   // strictly > 0 for finite logits
                }
            }
            __syncwarp();   // compute done before this stage is refilled (i+2)
        }
    }

    unsigned bits[PER];
    #pragma unroll
    for (int i = 0; i < PER; i++) bits[i] = __float_as_uint(ce_reg[i]);

    // Zero level-1 histogram (2048 bins); barrier also publishes scalar inits.
    s_hist[tid] = 0u;
    s_hist[tid + 1024] = 0u;
    __syncthreads();

    // Pos/psum block reduction and level-1 histogram share one barrier pair.
    {
        int   pc = (int)__reduce_add_sync(0xFFFFFFFFu, (unsigned)poscnt);
        float ps = psum;
        #pragma unroll
        for (int off = 16; off; off >>= 1)
            ps += __shfl_down_sync(0xFFFFFFFFu, ps, off);
        if (lane == 0) {
            atomicAdd(&s_pos, pc);
            atomicAdd(&s_psum, (double)ps);
        }
    }
    #pragma unroll
    for (int i = 0; i < PER; i++)
        hist_add(s_hist, bits[i] >> 20, 0xFFFFFFFFu);
    __syncthreads();

    const int npos = s_pos;
    const int k = min(3 * npos, AA - npos);   // uniform across block

    double negsum = 0.0;
    if (k > 0) {
        unsigned r = (unsigned)k;

        // ---- Level 1: bits[30:20], 2048 bins (2 per thread, pair scan) ----
        {
            const int p = 1023 - tid;               // pair index, tid0 = topmost
            const unsigned h_hi = s_hist[2 * p + 1];
            const unsigned h_lo = s_hist[2 * p];
            const unsigned P = h_hi + h_lo;
            const unsigned cum = block_scan_incl(P, s_w, wid, lane);
            const unsigned above = cum - P;         // count strictly above pair
            if (cum >= r && above < r) {
                if (above + h_hi >= r) { s_selbin = 2 * p + 1; s_selrank = r - above; }
                else                   { s_selbin = 2 * p;     s_selrank = r - above - h_hi; }
            }
        }
        __syncthreads();
        const unsigned B1 = (unsigned)s_selbin;
        r = s_selrank;
        __syncthreads();

        // ---- Level 2: bits[19:10] among level-1 bin == B1 ----
        s_hist[tid] = 0u;
        __syncthreads();
        #pragma unroll
        for (int i = 0; i < PER; i++) {
            const bool act = ((bits[i] >> 20) == B1);
            const unsigned mask = __ballot_sync(0xFFFFFFFFu, act);
            if (act) hist_add(s_hist, (bits[i] >> 10) & 1023u, mask);
        }
        __syncthreads();
        {
            const int bin = 1023 - tid;
            const unsigned h = s_hist[bin];
            const unsigned cum = block_scan_incl(h, s_w, wid, lane);
            if (cum >= r && cum - h < r) { s_selbin = bin; s_selrank = r - (cum - h); }
        }
        __syncthreads();
        const unsigned top21 = (B1 << 10) | (unsigned)s_selbin;
        r = s_selrank;
        __syncthreads();

        // ---- Level 3: bits[9:0] among top-21-bit match ----
        s_hist[tid] = 0u;
        __syncthreads();
        #pragma unroll
        for (int i = 0; i < PER; i++) {
            const bool act = ((bits[i] >> 10) == top21);
            const unsigned mask = __ballot_sync(0xFFFFFFFFu, act);
            if (act) hist_add(s_hist, bits[i] & 1023u, mask);
        }
        __syncthreads();
        {
            const int bin = 1023 - tid;
            const unsigned h = s_hist[bin];
            const unsigned cum = block_scan_incl(h, s_w, wid, lane);
            if (cum >= r && cum - h < r) { s_selbin = bin; s_selrank = r - (cum - h); }
        }
        // Zero scratch for a possible bisection fallback.
        if (tid < 64) s_hist[tid + 1024] = 0u;
        __syncthreads();

        unsigned vbits = ((unsigned)top21 << 10) | (unsigned)s_selbin;

        // ---- Exact validation: count(>v) < k <= count(>=v) ----
        {
            unsigned cgt = 0u, cge = 0u;
            #pragma unroll
            for (int i = 0; i < PER; i++) {
                cgt += (bits[i] >  vbits) ? 1u : 0u;
                cge += (bits[i] >= vbits) ? 1u : 0u;
            }
            cgt = __reduce_add_sync(0xFFFFFFFFu, cgt);
            cge = __reduce_add_sync(0xFFFFFFFFu, cge);
            if (lane == 0) {
                atomicAdd(&s_vgt, cgt);
                atomicAdd(&s_vge, cge);
            }
        }
        __syncthreads();
        const bool valid = (s_vgt < (unsigned)k) && (s_vge >= (unsigned)k);

        if (!valid) {
            // ---- Fallback: bisection on float bits (known-correct) ----
            unsigned lo = 0u, hi = 0x7F800000u;
            int iter = 0;
            while (lo < hi) {
                const unsigned mid = (lo + hi) >> 1;
                unsigned c = 0;
                #pragma unroll
                for (int i = 0; i < PER; i++) c += (bits[i] > mid) ? 1u : 0u;
                c = __reduce_add_sync(0xFFFFFFFFu, c);
                if (lane == 0) atomicAdd(&s_hist[1024 + iter], c);
                __syncthreads();
                const unsigned tot = s_hist[1024 + iter];
                if (tot < (unsigned)k) hi = mid; else lo = mid + 1u;
                iter++;
            }
            vbits = lo;
        }

        const float vth = __uint_as_float(vbits);

        // Sum of values strictly greater + tie fill at threshold.
        float    fs  = 0.f;
        unsigned cgt = 0u;
        #pragma unroll
        for (int i = 0; i < PER; i++)
            if (bits[i] > vbits) { fs += ce_reg[i]; cgt++; }
        cgt = __reduce_add_sync(0xFFFFFFFFu, cgt);
        #pragma unroll
        for (int off = 16; off; off >>= 1)
            fs += __shfl_down_sync(0xFFFFFFFFu, fs, off);
        if (lane == 0) {
            atomicAdd(&s_fsum, fs);
            atomicAdd(&s_cgt, cgt);
        }
        __syncthreads();
        negsum = (double)s_fsum + (double)(k - (int)s_cgt) * (double)vth;
    }

    // Publish per-row result; last block finalizes and resets the counter.
    if (tid == 0) {
        g_rowsum[b] = s_psum + negsum;
        g_rowpos[b] = npos;
        __threadfence();
        if (atomicAdd(&g_done, 1u) == ROWS - 1) s_last = 1;
    }
    __syncthreads();
    if (s_last) {
        double rs = 0.0; int rp = 0;
        if (tid < ROWS) {
            rs = ((volatile double*)g_rowsum)[tid];
            rp = ((volatile int*)g_rowpos)[tid];
        }
        #pragma unroll
        for (int off = 16; off; off >>= 1) {
            rs += __shfl_down_sync(0xFFFFFFFFu, rs, off);
            rp += __shfl_down_sync(0xFFFFFFFFu, rp, off);
        }
        if (tid < ROWS && lane == 0) { s_d[wid] = rs; s_i[wid] = rp; }
        __syncthreads();
        if (tid == 0) {
            const double tot = s_d[0] + s_d[1] + s_d[2] + s_d[3];
            const int    np  = s_i[0] + s_i[1] + s_i[2] + s_i[3];
            out[0] = (float)(tot / (double)np);
            g_done = 0u;   // reset for the next graph replay
        }
    }
}

extern "C" void kernel_launch(void* const* d_in, const int* in_sizes, int n_in,
                              void* d_out, int out_size)
{
    const float* conf = (const float*)d_in[0];
    const float* loc  = (const float*)d_in[1];
    const int*   lab  = (const int*)  d_in[2];
    const float* gloc = (const float*)d_in[3];
    float* out = (float*)d_out;

    const int dyn = 32 * 2 * 672 * (int)sizeof(float);   // 172032 B
    cudaFuncSetAttribute(mbl_fused, cudaFuncAttributeMaxDynamicSharedMemorySize, dyn);
    mbl_fused<<<ROWS, NT, dyn>>>(conf, loc, lab, gloc, out);
}

// round 15
// speedup vs baseline: 1.0662x; 1.0662x over previous
#include <cuda_runtime.h>
#include <cuda_bf16.h>

// MultiBoxLoss (SSD). 2-kernel split (fused variants plateaued at 2.9TB/s):
//  A) stream: per-anchor CE -> g_ce scratch; per-chunk (32 anchors) positive
//     count + (posCE + smoothL1) partials. Coalesced float4 smem staging,
//     front-batched __ldcs on ALL streamed inputs (keeps g_ce L2-resident).
//  B) per-row: reduce chunk partials -> k = min(3*npos, nneg); k-th largest
//     CE via block-parallel 3-level radix (11/10/10 bits) with prefix-sum bin
//     search; all block scalars reduced via per-warp slots (no contended
//     smem atomics, no smem double CAS); validated, bisection fallback.

#define ROWS 128
#define AA   8732
#define CC   21
#define CPR  273            // chunks per row: 272 full (32) + 1 partial (28)
#define TOTCH (ROWS * CPR)  // 34944
#define WPB  8              // warps per block in phase A
#define BLKA (TOTCH / WPB)  // 4368
#define NTB  1024
#define PER  9              // ceil(8732/1024)

__device__ float  g_ce[ROWS * AA];      // ce_neg (0 for positives)
__device__ int    g_chunk_pos[TOTCH];
__device__ float  g_chunk_sum[TOTCH];   // posCE + smoothL1 partial per chunk
__device__ double g_sum;
__device__ unsigned long long g_npos;
__device__ unsigned g_done;

// ---------------------------------------------------------------- Phase A
__global__ __launch_bounds__(256) void mbl_phaseA(
    const float* __restrict__ conf,
    const float* __restrict__ loc,
    const int*   __restrict__ lab,
    const float* __restrict__ gloc)
{
    __shared__ float sbuf[WPB * 672];   // 21504 B

    if (blockIdx.x == 0 && threadIdx.x == 0) {
        g_sum = 0.0; g_npos = 0ull; g_done = 0u;
    }

    const int wid  = threadIdx.x >> 5;
    const int lane = threadIdx.x & 31;
    const int chunk = blockIdx.x * WPB + wid;
    const int row = chunk / CPR;
    const int j   = chunk - row * CPR;
    const int na  = (j == CPR - 1) ? (AA - (CPR - 1) * 32) : 32;  // 28 or 32
    const size_t abase = (size_t)row * AA + (size_t)j * 32;
    const size_t idx = abase + (size_t)lane;

    // Issue label load early so it overlaps staging (streaming hint).
    const int lb = (lane < na) ? __ldcs(lab + idx) : 0;

    // Stage this chunk's logits: na*21 floats, contiguous & 16B-aligned.
    // Front-batch all LDGs into registers, then store to smem.
    float* sw = sbuf + wid * 672;
    const float4* src = (const float4*)(conf + abase * CC);
    const int n4 = (na * CC) >> 2;  // 168 or 147
    float4 q[6];
    #pragma unroll
    for (int i = 0; i < 6; i++) {
        const int t = lane + 32 * i;
        if (t < n4) q[i] = __ldcs(src + t);
    }
    #pragma unroll
    for (int i = 0; i < 6; i++) {
        const int t = lane + 32 * i;
        if (t < n4) ((float4*)sw)[t] = q[i];
    }
    __syncwarp();

    float cev = 0.f;    // ce_neg
    int   isp = 0;
    float psum = 0.f;   // posCE + smoothL1 contribution
    if (lane < na) {
        float v[CC];
        #pragma unroll
        for (int c = 0; c < CC; c++) v[c] = sw[lane * CC + c];

        float m = v[0];
        #pragma unroll
        for (int c = 1; c < CC; c++) m = fmaxf(m, v[c]);
        float s = 0.f;
        #pragma unroll
        for (int c = 0; c < CC; c++) s += __expf(v[c] - m);

        const float ce = m + __logf(s) - v[lb];

        if (lb > 0) {
            isp = 1;
            psum = ce;
            const float4 l4 = __ldcs((const float4*)loc  + idx);
            const float4 g4 = __ldcs((const float4*)gloc + idx);
            float d, ad;
            d = l4.x - g4.x; ad = fabsf(d); psum += (ad < 1.f) ? 0.5f * d * d : ad - 0.5f;
            d = l4.y - g4.y; ad = fabsf(d); psum += (ad < 1.f) ? 0.5f * d * d : ad - 0.5f;
            d = l4.z - g4.z; ad = fabsf(d); psum += (ad < 1.f) ? 0.5f * d * d : ad - 0.5f;
            d = l4.w - g4.w; ad = fabsf(d); psum += (ad < 1.f) ? 0.5f * d * d : ad - 0.5f;
        } else {
            cev = ce;   // strictly > 0 for finite logits
        }
        g_ce[idx] = cev;
    }

    // Warp-level chunk partials
    int pc = (int)__reduce_add_sync(0xFFFFFFFFu, (unsigned)isp);
    #pragma unroll
    for (int off = 16; off; off >>= 1)
        psum += __shfl_xor_sync(0xFFFFFFFFu, psum, off);
    if (lane == 0) {
        g_chunk_pos[chunk] = pc;
        g_chunk_sum[chunk] = psum;
    }
}

// ---------------------------------------------------------------- Phase B
// Warp-aggregated smem histogram add.
__device__ __forceinline__ void hist_add(unsigned* h, unsigned bin, unsigned mask)
{
    const unsigned peers  = __match_any_sync(mask, bin);
    const unsigned leader = __ffs(peers) - 1u;
    if ((threadIdx.x & 31u) == leader)
        atomicAdd(&h[bin], __popc(peers));
}

// Block-wide inclusive prefix sum over 1024 values (one per thread).
// Contains 2 __syncthreads. s_w must hold 32 unsigneds.
__device__ __forceinline__ unsigned block_scan_incl(
    unsigned v, unsigned* s_w, int wid, unsigned lane)
{
    #pragma unroll
    for (int off = 1; off < 32; off <<= 1) {
        const unsigned x = __shfl_up_sync(0xFFFFFFFFu, v, off);
        if (lane >= off) v += x;
    }
    if (lane == 31) s_w[wid] = v;
    __syncthreads();
    if (wid == 0) {
        unsigned t = s_w[lane];
        #pragma unroll
        for (int off = 1; off < 32; off <<= 1) {
            const unsigned x = __shfl_up_sync(0xFFFFFFFFu, t, off);
            if (lane >= off) t += x;
        }
        s_w[lane] = t;  // inclusive warp totals
    }
    __syncthreads();
    if (wid > 0) v += s_w[wid - 1];
    return v;
}

__global__ __launch_bounds__(NTB) void mbl_phaseB(float* __restrict__ out)
{
    const int b    = blockIdx.x;
    const int tid  = threadIdx.x;
    const int wid  = tid >> 5;
    const unsigned lane = tid & 31u;

    __shared__ unsigned s_hist[2048];
    __shared__ unsigned s_w[32];        // scan scratch
    __shared__ float    s_wf[32];       // per-warp float slots
    __shared__ int      s_wi[32];       // per-warp int slots
    __shared__ unsigned s_wu[32];       // per-warp unsigned slots
    __shared__ unsigned s_wu2[32];      // per-warp unsigned slots
    __shared__ int      s_selbin;
    __shared__ unsigned s_selrank;
    __shared__ int      s_pos;
    __shared__ float    s_psum;
    __shared__ float    s_fsum;
    __shared__ unsigned s_cgt;
    __shared__ unsigned s_vgt, s_vge;

    // Front-issue this row's ce_neg loads (L2-resident) to overlap below.
    float ce[PER];
    #pragma unroll
    for (int i = 0; i < PER; i++) {
        const int a = tid + i * NTB;
        ce[i] = (a < AA) ? __ldg(&g_ce[(size_t)b * AA + a]) : 0.f;
    }

    // Per-warp partial reduction of this row's chunk partials (no atomics).
    {
        int   pc = 0;
        float ps = 0.f;
        if (tid < CPR) {
            pc = g_chunk_pos[b * CPR + tid];
            ps = g_chunk_sum[b * CPR + tid];
        }
        pc = (int)__reduce_add_sync(0xFFFFFFFFu, (unsigned)pc);
        #pragma unroll
        for (int off = 16; off; off >>= 1)
            ps += __shfl_down_sync(0xFFFFFFFFu, ps, off);
        if (lane == 0) { s_wi[wid] = pc; s_wf[wid] = ps; }
    }

    unsigned bits[PER];
    #pragma unroll
    for (int i = 0; i < PER; i++) bits[i] = __float_as_uint(ce[i]);

    // Zero level-1 histogram (2048 bins).
    s_hist[tid] = 0u;
    s_hist[tid + 1024] = 0u;
    __syncthreads();   // partial slots + zeroed hist visible

    // Level-1 histogram; warp 0 also folds the per-warp partial slots.
    #pragma unroll
    for (int i = 0; i < PER; i++)
        hist_add(s_hist, bits[i] >> 20, 0xFFFFFFFFu);
    if (wid == 0) {
        int   p = s_wi[lane];
        float f = s_wf[lane];
        p = (int)__reduce_add_sync(0xFFFFFFFFu, (unsigned)p);
        #pragma unroll
        for (int off = 16; off; off >>= 1)
            f += __shfl_down_sync(0xFFFFFFFFu, f, off);
        if (lane == 0) { s_pos = p; s_psum = f; }
    }
    __syncthreads();

    const int npos = s_pos;
    const int k = min(3 * npos, AA - npos);   // uniform across block

    double negsum = 0.0;
    if (k > 0) {
        unsigned r = (unsigned)k;

        // ---- Level 1: bits[30:20], 2048 bins (2 per thread, pair scan) ----
        {
            const int p = 1023 - tid;               // pair index, tid0 = topmost
            const unsigned h_hi = s_hist[2 * p + 1];
            const unsigned h_lo = s_hist[2 * p];
            const unsigned P = h_hi + h_lo;
            const unsigned cum = block_scan_incl(P, s_w, wid, lane);
            const unsigned above = cum - P;         // count strictly above pair
            if (cum >= r && above < r) {
                if (above + h_hi >= r) { s_selbin = 2 * p + 1; s_selrank = r - above; }
                else                   { s_selbin = 2 * p;     s_selrank = r - above - h_hi; }
            }
        }
        __syncthreads();
        const unsigned B1 = (unsigned)s_selbin;
        r = s_selrank;
        __syncthreads();

        // ---- Level 2: bits[19:10] among level-1 bin == B1 ----
        s_hist[tid] = 0u;
        __syncthreads();
        #pragma unroll
        for (int i = 0; i < PER; i++) {
            const bool act = ((bits[i] >> 20) == B1);
            const unsigned mask = __ballot_sync(0xFFFFFFFFu, act);
            if (act) hist_add(s_hist, (bits[i] >> 10) & 1023u, mask);
        }
        __syncthreads();
        {
            const int bin = 1023 - tid;
            const unsigned h = s_hist[bin];
            const unsigned cum = block_scan_incl(h, s_w, wid, lane);
            if (cum >= r && cum - h < r) { s_selbin = bin; s_selrank = r - (cum - h); }
        }
        __syncthreads();
        const unsigned top21 = (B1 << 10) | (unsigned)s_selbin;
        r = s_selrank;
        __syncthreads();

        // ---- Level 3: bits[9:0] among top-21-bit match ----
        s_hist[tid] = 0u;
        __syncthreads();
        #pragma unroll
        for (int i = 0; i < PER; i++) {
            const bool act = ((bits[i] >> 10) == top21);
            const unsigned mask = __ballot_sync(0xFFFFFFFFu, act);
            if (act) hist_add(s_hist, bits[i] & 1023u, mask);
        }
        __syncthreads();
        {
            const int bin = 1023 - tid;
            const unsigned h = s_hist[bin];
            const unsigned cum = block_scan_incl(h, s_w, wid, lane);
            if (cum >= r && cum - h < r) { s_selbin = bin; s_selrank = r - (cum - h); }
        }
        // Zero scratch for a possible bisection fallback.
        if (tid < 64) s_hist[tid + 1024] = 0u;
        __syncthreads();

        unsigned vbits = ((unsigned)top21 << 10) | (unsigned)s_selbin;

        // ---- Exact validation (per-warp slots): count(>v) < k <= count(>=v) ----
        {
            unsigned cgt = 0u, cge = 0u;
            #pragma unroll
            for (int i = 0; i < PER; i++) {
                cgt += (bits[i] >  vbits) ? 1u : 0u;
                cge += (bits[i] >= vbits) ? 1u : 0u;
            }
            cgt = __reduce_add_sync(0xFFFFFFFFu, cgt);
            cge = __reduce_add_sync(0xFFFFFFFFu, cge);
            if (lane == 0) { s_wu[wid] = cgt; s_wu2[wid] = cge; }
        }
        __syncthreads();
        if (tid < 32) {
            unsigned a = __reduce_add_sync(0xFFFFFFFFu, s_wu[lane]);
            unsigned e = __reduce_add_sync(0xFFFFFFFFu, s_wu2[lane]);
            if (lane == 0) { s_vgt = a; s_vge = e; }
        }
        __syncthreads();
        const bool valid = (s_vgt < (unsigned)k) && (s_vge >= (unsigned)k);

        if (!valid) {
            // ---- Fallback: bisection on float bits (known-correct) ----
            unsigned lo = 0u, hi = 0x7F800000u;
            int iter = 0;
            while (lo < hi) {
                const unsigned mid = (lo + hi) >> 1;
                unsigned c = 0;
                #pragma unroll
                for (int i = 0; i < PER; i++) c += (bits[i] > mid) ? 1u : 0u;
                c = __reduce_add_sync(0xFFFFFFFFu, c);
                if (lane == 0) atomicAdd(&s_hist[1024 + iter], c);
                __syncthreads();
                const unsigned tot = s_hist[1024 + iter];
                if (tot < (unsigned)k) hi = mid; else lo = mid + 1u;
                iter++;
            }
            vbits = lo;
        }

        const float vth = __uint_as_float(vbits);

        // Sum of values strictly greater + tie fill (per-warp slots).
        float    fs  = 0.f;
        unsigned cgt = 0u;
        #pragma unroll
        for (int i = 0; i < PER; i++)
            if (bits[i] > vbits) { fs += ce[i]; cgt++; }
        cgt = __reduce_add_sync(0xFFFFFFFFu, cgt);
        #pragma unroll
        for (int off = 16; off; off >>= 1)
            fs += __shfl_down_sync(0xFFFFFFFFu, fs, off);
        if (lane == 0) { s_wf[wid] = fs; s_wu[wid] = cgt; }
        __syncthreads();
        if (tid < 32) {
            unsigned c = __reduce_add_sync(0xFFFFFFFFu, s_wu[lane]);
            float    f = s_wf[lane];
            #pragma unroll
            for (int off = 16; off; off >>= 1)
                f += __shfl_down_sync(0xFFFFFFFFu, f, off);
            if (lane == 0) { s_fsum = f; s_cgt = c; }
        }
        __syncthreads();
        negsum = (double)s_fsum + (double)(k - (int)s_cgt) * (double)vth;
    }

    if (tid == 0) {
        atomicAdd(&g_sum, (double)s_psum + negsum);
        atomicAdd(&g_npos, (unsigned long long)npos);
        __threadfence();
        const unsigned done = atomicAdd(&g_done, 1u);
        if (done == ROWS - 1) {
            __threadfence();
            const double ts = atomicAdd(&g_sum, 0.0);
            const unsigned long long tp = atomicAdd(&g_npos, 0ull);
            out[0] = (float)(ts / (double)tp);
        }
    }
}

extern "C" void kernel_launch(void* const* d_in, const int* in_sizes, int n_in,
                              void* d_out, int out_size)
{
    const float* conf = (const float*)d_in[0];
    const float* loc  = (const float*)d_in[1];
    const int*   lab  = (const int*)  d_in[2];
    const float* gloc = (const float*)d_in[3];
    float* out = (float*)d_out;

    mbl_phaseA<<<BLKA, 256>>>(conf, loc, lab, gloc);
    mbl_phaseB<<<ROWS, NTB>>>(out);
}